// round 4
// baseline (speedup 1.0000x reference)
#include <cuda_runtime.h>

#define Lg 2048
#define LMASK 2047
#define LSHIFT 11
#define NCELL (Lg * Lg)

#define R_OVER_5 0.5554f      /* 2.777 / 5 */
#define ETA 0.8f
#define ONE_MINUS_ETA 0.2f
#define GAMMA 0.8f
#define INV_K 2.0f            /* 1 / 0.5 */

// 16 MB scratch for the fermi profit matrix (upd), static device array (no alloc).
__device__ float g_upd[NCELL];

// ---------------------------------------------------------------------------
// Kernel A: profit (13-point stencil, fused double plus-conv) + Q update.
// 8 cells per thread. Stencil via 16 aligned int4 loads; Q streamed with .cs.
// ---------------------------------------------------------------------------
__global__ __launch_bounds__(256) void spgg_payoff_qupdate(
    const int4* __restrict__ tm4,        // type_t_minus as int4
    const int4* __restrict__ t4,         // type_t as int4
    const float4* __restrict__ Q,        // [N] rows of 4 floats
    float4* __restrict__ Q_out,
    float4* __restrict__ prof4)
{
    int i8 = blockIdx.x * blockDim.x + threadIdx.x;   // 0 .. N/8-1
    int row  = i8 >> 8;            // 2048/8 = 256 groups per row
    int colg = (i8 & 255) << 3;    // first column of this 8-cell group

    int b0  = (row << LSHIFT) >> 2;
    int bm1 = (((row - 1) & LMASK) << LSHIFT) >> 2;
    int bp1 = (((row + 1) & LMASK) << LSHIFT) >> 2;
    int bm2 = (((row - 2) & LMASK) << LSHIFT) >> 2;
    int bp2 = (((row + 2) & LMASK) << LSHIFT) >> 2;

    int cL  = ((colg - 4) & LMASK) >> 2;
    int cC0 = colg >> 2;
    int cC1 = cC0 + 1;
    int cR  = ((colg + 8) & LMASK) >> 2;

    // Batched independent stencil loads (16 int4)
    int4 A0L = __ldg(t4 + b0  + cL), A0C0 = __ldg(t4 + b0  + cC0), A0C1 = __ldg(t4 + b0  + cC1), A0R = __ldg(t4 + b0  + cR);
    int4 M1L = __ldg(t4 + bm1 + cL), M1C0 = __ldg(t4 + bm1 + cC0), M1C1 = __ldg(t4 + bm1 + cC1), M1R = __ldg(t4 + bm1 + cR);
    int4 P1L = __ldg(t4 + bp1 + cL), P1C0 = __ldg(t4 + bp1 + cC0), P1C1 = __ldg(t4 + bp1 + cC1), P1R = __ldg(t4 + bp1 + cR);
    int4 M2C0 = __ldg(t4 + bm2 + cC0), M2C1 = __ldg(t4 + bm2 + cC1);
    int4 P2C0 = __ldg(t4 + bp2 + cC0), P2C1 = __ldg(t4 + bp2 + cC1);

    // 16-wide windows: index k corresponds to column colg-4+k
    int w0[16] = {A0L.x,A0L.y,A0L.z,A0L.w, A0C0.x,A0C0.y,A0C0.z,A0C0.w,
                  A0C1.x,A0C1.y,A0C1.z,A0C1.w, A0R.x,A0R.y,A0R.z,A0R.w};
    int wm[16] = {M1L.x,M1L.y,M1L.z,M1L.w, M1C0.x,M1C0.y,M1C0.z,M1C0.w,
                  M1C1.x,M1C1.y,M1C1.z,M1C1.w, M1R.x,M1R.y,M1R.z,M1R.w};
    int wp[16] = {P1L.x,P1L.y,P1L.z,P1L.w, P1C0.x,P1C0.y,P1C0.z,P1C0.w,
                  P1C1.x,P1C1.y,P1C1.z,P1C1.w, P1R.x,P1R.y,P1R.z,P1R.w};
    int u2[8]  = {M2C0.x,M2C0.y,M2C0.z,M2C0.w, M2C1.x,M2C1.y,M2C1.z,M2C1.w};
    int d2[8]  = {P2C0.x,P2C0.y,P2C0.z,P2C0.w, P2C1.x,P2C1.y,P2C1.z,P2C1.w};

    // Compute the 8 profits first (frees the stencil windows)
    float pr[8];
    int   t00a[8];
    #pragma unroll
    for (int j = 0; j < 8; j++) {
        int k = j + 4;
        int t00  = w0[k];
        int orth = w0[k-1] + w0[k+1] + wm[k] + wp[k];
        int diag = wm[k-1] + wm[k+1] + wp[k-1] + wp[k+1];
        int far  = w0[k-2] + w0[k+2] + u2[j] + d2[j];
        int S2   = 5 * t00 + 2 * (orth + diag) + far;
        pr[j]   = (float)S2 * R_OVER_5 - 5.0f * (float)t00;
        t00a[j] = t00;
    }

    // Q rows: pure stream, no reuse -> evict-first (.cs)
    size_t base = (size_t)i8 << 3;
    float4 qv[8];
    #pragma unroll
    for (int j = 0; j < 8; j++) qv[j] = __ldcs(Q + base + j);

    int4 Av0 = __ldcs(tm4 + (i8 << 1));
    int4 Av1 = __ldcs(tm4 + (i8 << 1) + 1);
    int Aarr[8] = {Av0.x, Av0.y, Av0.z, Av0.w, Av1.x, Av1.y, Av1.z, Av1.w};

    float up[8];
    #pragma unroll
    for (int j = 0; j < 8; j++) {
        float4 q = qv[j];
        int A = Aarr[j];
        int B = t00a[j];
        float maxv = B ? fmaxf(q.z, q.w) : fmaxf(q.x, q.y);
        float old  = B ? (A ? q.w : q.y) : (A ? q.z : q.x);
        float upd  = ONE_MINUS_ETA * old + ETA * (pr[j] + GAMMA * maxv);
        if (A == 0) { if (B == 0) q.x = upd; else q.y = upd; }
        else        { if (B == 0) q.z = upd; else q.w = upd; }
        qv[j] = q;
        up[j] = upd;
    }

    #pragma unroll
    for (int j = 0; j < 8; j++) __stcs(Q_out + base + j, qv[j]);

    __stcs(prof4 + (i8 << 1),     make_float4(pr[0], pr[1], pr[2], pr[3]));
    __stcs(prof4 + (i8 << 1) + 1, make_float4(pr[4], pr[5], pr[6], pr[7]));
    // g_upd is re-read (gathered) by kernel B -> default policy (keep in L2)
    reinterpret_cast<float4*>(g_upd)[(i8 << 1)]     = make_float4(up[0], up[1], up[2], up[3]);
    reinterpret_cast<float4*>(g_upd)[(i8 << 1) + 1] = make_float4(up[4], up[5], up[6], up[7]);
}

// ---------------------------------------------------------------------------
// Kernel B: fermi update, 8 cells per thread, 16 independent gathers batched
// ---------------------------------------------------------------------------
__global__ __launch_bounds__(256) void spgg_fermi(
    const int* __restrict__ type_t,
    const int4* __restrict__ t4,
    const int4* __restrict__ ld4,
    const float4* __restrict__ lp4,
    float4* __restrict__ type_out)
{
    int i8 = blockIdx.x * blockDim.x + threadIdx.x;   // 0 .. N/8-1
    int row  = i8 >> 8;
    int colg = (i8 & 255) << 3;
    int r0 = row << LSHIFT;

    int4   d0 = __ldcs(ld4 + (i8 << 1)),     d1 = __ldcs(ld4 + (i8 << 1) + 1);
    float4 p0 = __ldcs(lp4 + (i8 << 1)),     p1 = __ldcs(lp4 + (i8 << 1) + 1);
    int4   t0 = __ldg (t4  + (i8 << 1)),     t1 = __ldg (t4  + (i8 << 1) + 1);
    float4 u0 = reinterpret_cast<const float4*>(g_upd)[(i8 << 1)];
    float4 u1 = reinterpret_cast<const float4*>(g_upd)[(i8 << 1) + 1];

    int dv[8]   = {d0.x,d0.y,d0.z,d0.w, d1.x,d1.y,d1.z,d1.w};
    int tv[8]   = {t0.x,t0.y,t0.z,t0.w, t1.x,t1.y,t1.z,t1.w};
    float uv[8] = {u0.x,u0.y,u0.z,u0.w, u1.x,u1.y,u1.z,u1.w};
    float pv[8] = {p0.x,p0.y,p0.z,p0.w, p1.x,p1.y,p1.z,p1.w};

    int rm1 = ((row - 1) & LMASK) << LSHIFT;
    int rp1 = ((row + 1) & LMASK) << LSHIFT;

    int ni[8];
    #pragma unroll
    for (int j = 0; j < 8; j++) {
        int col = colg + j;
        int d = dv[j];
        int nr = r0, nc = col;
        if (d == 0)      nc = (col - 1) & LMASK;
        else if (d == 1) nc = (col + 1) & LMASK;
        else if (d == 2) nr = rm1;
        else             nr = rp1;
        ni[j] = nr | nc;
    }

    // Batch all 16 independent gathers before consuming any
    float un[8];
    int   tn[8];
    #pragma unroll
    for (int j = 0; j < 8; j++) un[j] = g_upd[ni[j]];
    #pragma unroll
    for (int j = 0; j < 8; j++) tn[j] = __ldg(type_t + ni[j]);

    float ov[8];
    #pragma unroll
    for (int j = 0; j < 8; j++) {
        float W = 1.0f / (1.0f + __expf((uv[j] - un[j]) * INV_K));
        ov[j] = (float)((pv[j] <= W) ? tn[j] : tv[j]);
    }

    __stcs(type_out + (i8 << 1),     make_float4(ov[0], ov[1], ov[2], ov[3]));
    __stcs(type_out + (i8 << 1) + 1, make_float4(ov[4], ov[5], ov[6], ov[7]));
}

// ---------------------------------------------------------------------------
// Launch: output layout = concat(Q_new[4N], type_t1[N], profit[N]) as float32
// ---------------------------------------------------------------------------
extern "C" void kernel_launch(void* const* d_in, const int* in_sizes, int n_in,
                              void* d_out, int out_size)
{
    const int4*   tm4   = (const int4*)   d_in[0];
    const int4*   t4    = (const int4*)   d_in[1];
    const float4* Q     = (const float4*) d_in[2];
    const int4*   ld4   = (const int4*)   d_in[3];
    const float4* lp4   = (const float4*) d_in[4];

    float* out        = (float*)d_out;
    float4* Q_out     = (float4*)out;                          // [0, 4N)
    float4* type_out  = (float4*)(out + 4 * (size_t)NCELL);    // [4N, 5N)
    float4* prof4     = (float4*)(out + 5 * (size_t)NCELL);    // [5N, 6N)

    const int threads = 256;
    const int blocks  = (NCELL / 8) / threads;   // 2048

    spgg_payoff_qupdate<<<blocks, threads>>>(tm4, t4, Q, Q_out, prof4);
    spgg_fermi<<<blocks, threads>>>((const int*)d_in[1], t4, ld4, lp4, type_out);
}

// round 5
// speedup vs baseline: 1.4547x; 1.4547x over previous
#include <cuda_runtime.h>

#define Lg 2048
#define LMASK 2047
#define LSHIFT 11
#define NCELL (Lg * Lg)

#define R_OVER_5 0.5554f      /* 2.777 / 5 */
#define ETA 0.8f
#define ONE_MINUS_ETA 0.2f
#define GAMMA 0.8f
#define INV_K 2.0f            /* 1 / 0.5 */

// 16 MB scratch for the fermi profit matrix (upd), static device array (no alloc).
__device__ float g_upd[NCELL];

// ---------------------------------------------------------------------------
// Kernel A: profit (13-point stencil, fused double plus-conv) + Q update.
// Scalar (1 cell/thread): low regs, high occupancy — measured fastest config.
// Q stream gets evict-first (.cs) so it doesn't thrash L2 reuse of type_t/g_upd.
// ---------------------------------------------------------------------------
__global__ __launch_bounds__(256) void spgg_payoff_qupdate(
    const int* __restrict__ type_tm,      // type_t_minus
    const int* __restrict__ type_t,
    const float4* __restrict__ Q,         // [N] rows of 4 floats
    float4* __restrict__ Q_out,
    float* __restrict__ profit_out)
{
    int i = blockIdx.x * blockDim.x + threadIdx.x;

    int row = i >> LSHIFT;
    int col = i & LMASK;

    int rm1 = ((row - 1) & LMASK) << LSHIFT;
    int rp1 = ((row + 1) & LMASK) << LSHIFT;
    int rm2 = ((row - 2) & LMASK) << LSHIFT;
    int rp2 = ((row + 2) & LMASK) << LSHIFT;
    int r0  = row << LSHIFT;

    int cm1 = (col - 1) & LMASK;
    int cp1 = (col + 1) & LMASK;
    int cm2 = (col - 2) & LMASK;
    int cp2 = (col + 2) & LMASK;

    // weights of (plus ∘ plus): center 5; orth dist-1: 2; diagonals: 2; dist-2: 1
    int t00 = __ldg(type_t + r0 + col);
    int orth = __ldg(type_t + r0 + cm1) + __ldg(type_t + r0 + cp1)
             + __ldg(type_t + rm1 + col) + __ldg(type_t + rp1 + col);
    int diag = __ldg(type_t + rm1 + cm1) + __ldg(type_t + rm1 + cp1)
             + __ldg(type_t + rp1 + cm1) + __ldg(type_t + rp1 + cp1);
    int far2 = __ldg(type_t + r0 + cm2) + __ldg(type_t + r0 + cp2)
             + __ldg(type_t + rm2 + col) + __ldg(type_t + rp2 + col);

    int S2 = 5 * t00 + 2 * (orth + diag) + far2;
    float profit = (float)S2 * R_OVER_5 - 5.0f * (float)t00;

    // ---- Q update (Q rows are a pure stream: evict-first) ----
    float4 q = __ldcs(Q + i);        // (Q00, Q01, Q10, Q11)
    int A = __ldcs(type_tm + i);
    int B = t00;

    float maxv = B ? fmaxf(q.z, q.w) : fmaxf(q.x, q.y);
    float old  = B ? (A ? q.w : q.y) : (A ? q.z : q.x);
    float upd  = ONE_MINUS_ETA * old + ETA * (profit + GAMMA * maxv);

    if (A == 0) { if (B == 0) q.x = upd; else q.y = upd; }
    else        { if (B == 0) q.z = upd; else q.w = upd; }

    __stcs(Q_out + i, q);
    __stcs(profit_out + i, profit);
    g_upd[i] = upd;                  // re-read by kernel B: keep in L2
}

// ---------------------------------------------------------------------------
// Kernel B: fermi update, 4 cells per thread, gathers batched for MLP
// (measured best config: 32 regs, occ ~85%)
// ---------------------------------------------------------------------------
__global__ __launch_bounds__(256) void spgg_fermi(
    const int* __restrict__ type_t,
    const int4* __restrict__ t4,
    const int4* __restrict__ ld4,
    const float4* __restrict__ lp4,
    float4* __restrict__ type_out)
{
    int i4 = blockIdx.x * blockDim.x + threadIdx.x;
    int row  = i4 >> 9;
    int colg = (i4 & 511) << 2;
    int r0 = row << LSHIFT;

    int4   dir  = __ldg(ld4 + i4);
    float4 prob = __ldg(lp4 + i4);
    int4   tt   = __ldg(t4 + i4);
    float4 uu   = reinterpret_cast<const float4*>(g_upd)[i4];

    int dv[4] = {dir.x, dir.y, dir.z, dir.w};
    int tv[4] = {tt.x, tt.y, tt.z, tt.w};
    float uv[4] = {uu.x, uu.y, uu.z, uu.w};
    float pv[4] = {prob.x, prob.y, prob.z, prob.w};

    // Compute neighbor indices first, then batch the 8 independent gathers.
    int ni[4];
    #pragma unroll
    for (int j = 0; j < 4; j++) {
        int col = colg + j;
        int d = dv[j];
        int nr = r0, nc = col;
        if (d == 0)      nc = (col - 1) & LMASK;
        else if (d == 1) nc = (col + 1) & LMASK;
        else if (d == 2) nr = ((row - 1) & LMASK) << LSHIFT;
        else             nr = ((row + 1) & LMASK) << LSHIFT;
        ni[j] = nr | nc;
    }

    float un[4];
    int   tn[4];
    #pragma unroll
    for (int j = 0; j < 4; j++) un[j] = g_upd[ni[j]];
    #pragma unroll
    for (int j = 0; j < 4; j++) tn[j] = __ldg(type_t + ni[j]);

    float ov[4];
    #pragma unroll
    for (int j = 0; j < 4; j++) {
        float W = 1.0f / (1.0f + __expf((uv[j] - un[j]) * INV_K));
        ov[j] = (float)((pv[j] <= W) ? tn[j] : tv[j]);
    }

    type_out[i4] = make_float4(ov[0], ov[1], ov[2], ov[3]);
}

// ---------------------------------------------------------------------------
// Launch: output layout = concat(Q_new[4N], type_t1[N], profit[N]) as float32
// ---------------------------------------------------------------------------
extern "C" void kernel_launch(void* const* d_in, const int* in_sizes, int n_in,
                              void* d_out, int out_size)
{
    const int*    type_tm = (const int*)   d_in[0];
    const int*    type_t  = (const int*)   d_in[1];
    const int4*   t4      = (const int4*)  d_in[1];
    const float4* Q       = (const float4*)d_in[2];
    const int4*   ld4     = (const int4*)  d_in[3];
    const float4* lp4     = (const float4*)d_in[4];

    float* out        = (float*)d_out;
    float4* Q_out     = (float4*)out;                          // [0, 4N)
    float4* type_out  = (float4*)(out + 4 * (size_t)NCELL);    // [4N, 5N)
    float* profit_out = out + 5 * (size_t)NCELL;               // [5N, 6N)

    const int threads = 256;

    spgg_payoff_qupdate<<<NCELL / threads, threads>>>(type_tm, type_t, Q, Q_out, profit_out);
    spgg_fermi<<<(NCELL / 4) / threads, threads>>>(type_t, t4, ld4, lp4, type_out);
}

// round 6
// speedup vs baseline: 1.4592x; 1.0031x over previous
#include <cuda_runtime.h>

#define Lg 2048
#define LMASK 2047
#define LSHIFT 11
#define NCELL (Lg * Lg)

#define R_OVER_5 0.5554f      /* 2.777 / 5 */
#define ETA 0.8f
#define ONE_MINUS_ETA 0.2f
#define GAMMA 0.8f
#define INV_K 2.0f            /* 1 / 0.5 */

// Tile geometry
#define TX 64
#define TY 16
#define R1 (TY + 6)            /* type rows staged (3-halo)      = 22 */
#define C1 (TX + 6)            /* type cols staged               = 70 */
#define TSTR 72                /* type smem row stride (padded)  */
#define R2 (TY + 2)            /* upd rows computed (1-halo)     = 18 */
#define C2 (TX + 2)            /* upd cols computed              = 66 */
#define USTR 68                /* upd smem row stride            */

// ---------------------------------------------------------------------------
// Fused kernel: stage type tile, compute profit+Q-update for tile+1halo,
// then fermi entirely from shared memory. One pass over all streams.
// ---------------------------------------------------------------------------
__global__ __launch_bounds__(256) void spgg_fused(
    const int* __restrict__ type_tm,
    const int* __restrict__ type_t,
    const float4* __restrict__ Q,
    const int* __restrict__ ldir,
    const float* __restrict__ lprob,
    float4* __restrict__ Q_out,
    float* __restrict__ type_out,
    float* __restrict__ profit_out)
{
    __shared__ int   s_type[R1 * TSTR];
    __shared__ float s_upd [R2 * USTR];

    int tid  = threadIdx.x;
    int bx   = blockIdx.x & 31;    // 2048/64 = 32 column tiles
    int by   = blockIdx.x >> 5;    // 128 row tiles
    int row0 = by * TY;
    int col0 = bx * TX;

    // ---- Phase 1: stage type_t (tile + 3-halo), wrap-indexed ----
    #pragma unroll 2
    for (int idx = tid; idx < R1 * C1; idx += 256) {
        int r = idx / C1;
        int c = idx - r * C1;
        int gr = (row0 - 3 + r) & LMASK;
        int gc = (col0 - 3 + c) & LMASK;
        s_type[r * TSTR + c] = __ldg(type_t + (gr << LSHIFT) + gc);
    }
    __syncthreads();

    // ---- Phase 2: profit (13-pt stencil from smem) + Q update for tile+1halo ----
    #pragma unroll 2
    for (int idx = tid; idx < R2 * C2; idx += 256) {
        int r = idx / C2;
        int c = idx - r * C2;

        const int* st = s_type + (r + 2) * TSTR + (c + 2);
        int t00  = st[0];
        int orth = st[-1] + st[1] + st[-TSTR] + st[TSTR];
        int diag = st[-TSTR - 1] + st[-TSTR + 1] + st[TSTR - 1] + st[TSTR + 1];
        int far2 = st[-2] + st[2] + st[-2 * TSTR] + st[2 * TSTR];
        int S2   = 5 * t00 + 2 * (orth + diag) + far2;
        float profit = (float)S2 * R_OVER_5 - 5.0f * (float)t00;

        int gr = (row0 - 1 + r) & LMASK;
        int gc = (col0 - 1 + c) & LMASK;
        int gidx = (gr << LSHIFT) | gc;

        float4 q = __ldcs(Q + gidx);           // pure stream: evict-first
        int A = __ldg(type_tm + gidx);
        int B = t00;

        float maxv = B ? fmaxf(q.z, q.w) : fmaxf(q.x, q.y);
        float old  = B ? (A ? q.w : q.y) : (A ? q.z : q.x);
        float upd  = ONE_MINUS_ETA * old + ETA * (profit + GAMMA * maxv);

        if (A == 0) { if (B == 0) q.x = upd; else q.y = upd; }
        else        { if (B == 0) q.z = upd; else q.w = upd; }

        s_upd[r * USTR + c] = upd;

        // inner-tile cells write the streamed outputs
        if ((unsigned)(r - 1) < TY && (unsigned)(c - 1) < TX) {
            __stcs(Q_out + gidx, q);
            __stcs(profit_out + gidx, profit);
        }
    }
    __syncthreads();

    // ---- Phase 3: fermi update from smem ----
    #pragma unroll
    for (int idx = tid; idx < TY * TX; idx += 256) {
        int tr = idx >> 6;       // TX = 64
        int tc = idx & 63;
        int gidx = ((row0 + tr) << LSHIFT) | (col0 + tc);

        int   d = __ldcs(ldir + gidx);
        float p = __ldcs(lprob + gidx);

        // my cell in upd coords: (tr+1, tc+1); in type coords: (tr+3, tc+3)
        float u = s_upd[(tr + 1) * USTR + (tc + 1)];

        int ur, uc;
        if (d == 0)      { ur = tr + 1; uc = tc;     }   // col-1
        else if (d == 1) { ur = tr + 1; uc = tc + 2; }   // col+1
        else if (d == 2) { ur = tr;     uc = tc + 1; }   // row-1
        else             { ur = tr + 2; uc = tc + 1; }   // row+1

        float un = s_upd[ur * USTR + uc];
        int tmine = s_type[(tr + 3) * TSTR + (tc + 3)];
        int tn    = s_type[(ur + 2) * TSTR + (uc + 2)];  // upd(r,c) -> type(r+2,c+2)

        float W = 1.0f / (1.0f + __expf((u - un) * INV_K));
        int out = (p <= W) ? tn : tmine;
        __stcs(type_out + gidx, (float)out);
    }
}

// ---------------------------------------------------------------------------
// Launch: output layout = concat(Q_new[4N], type_t1[N], profit[N]) as float32
// ---------------------------------------------------------------------------
extern "C" void kernel_launch(void* const* d_in, const int* in_sizes, int n_in,
                              void* d_out, int out_size)
{
    const int*    type_tm = (const int*)   d_in[0];
    const int*    type_t  = (const int*)   d_in[1];
    const float4* Q       = (const float4*)d_in[2];
    const int*    ldir    = (const int*)   d_in[3];
    const float*  lprob   = (const float*) d_in[4];

    float* out        = (float*)d_out;
    float4* Q_out     = (float4*)out;                 // [0, 4N)
    float* type_out   = out + 4 * (size_t)NCELL;      // [4N, 5N)
    float* profit_out = out + 5 * (size_t)NCELL;      // [5N, 6N)

    const int blocks = (Lg / TX) * (Lg / TY);         // 32 * 128 = 4096

    spgg_fused<<<blocks, 256>>>(type_tm, type_t, Q, ldir, lprob,
                                Q_out, type_out, profit_out);
}

// round 7
// speedup vs baseline: 1.5782x; 1.0816x over previous
#include <cuda_runtime.h>

#define Lg 2048
#define LMASK 2047
#define LSHIFT 11
#define NCELL (Lg * Lg)

#define R_OVER_5 0.5554f      /* 2.777 / 5 */
#define ETA 0.8f
#define ONE_MINUS_ETA 0.2f
#define GAMMA 0.8f
#define INV_K 2.0f            /* 1 / 0.5 */

// Tile geometry: 64 wide x 16 tall, 256 threads, 4 inner cells/thread
#define TX 64
#define TY 16
// type staging: rows row0-3 .. row0+18 (22), cols col0-4 .. col0+71 (76 = 19 int4)
#define TROWS 22
#define TV4   19               /* int4 per staged row */
#define TSTR4 20               /* padded stride in int4 */
#define TSTR  80               /* padded stride in ints */
// upd: rows row0-1 .. row0+16 (18), cols col0-1 .. col0+64 (66)
#define UROWS 18
#define UCOLS 66
#define USTR  68
#define NHALO 164              /* 18*66 - 16*64 ring cells */

__global__ __launch_bounds__(256) void spgg_fused(
    const int* __restrict__ type_tm,
    const int* __restrict__ type_t,
    const float4* __restrict__ Q,
    const int* __restrict__ ldir,
    const float* __restrict__ lprob,
    float4* __restrict__ Q_out,
    float* __restrict__ type_out,
    float* __restrict__ profit_out)
{
    __shared__ int4  s_type4[TROWS * TSTR4];
    __shared__ float s_upd  [UROWS * USTR];
    const int* s_type = (const int*)s_type4;

    int tid  = threadIdx.x;
    int bx   = blockIdx.x & 31;    // 32 column tiles
    int by   = blockIdx.x >> 5;    // 128 row tiles
    int row0 = by * TY;
    int col0 = bx * TX;

    int tr0 = tid >> 6;            // 0..3
    int tc  = tid & 63;

    // ---- Issue phase-1 staging loads (int4, wrap at int4 granularity) ----
    int4 stage[2];
    int  sidx[2];
    #pragma unroll
    for (int k = 0; k < 2; k++) {
        int idx = tid + k * 256;
        if (idx < TROWS * TV4) {
            int r  = idx / TV4;
            int c4 = idx - r * TV4;
            int gr = (row0 - 3 + r) & LMASK;
            int gc = (col0 - 4 + (c4 << 2)) & LMASK;
            stage[k] = __ldg((const int4*)(type_t + (gr << LSHIFT) + gc));
            sidx[k]  = r * TSTR4 + c4;
        } else sidx[k] = -1;
    }

    // ---- Prefetch inner-cell streams (4 cells per thread, fixed mapping) ----
    int gidx[4];
    float4 qv[4];
    int av[4];
    #pragma unroll
    for (int j = 0; j < 4; j++) {
        int tr = (tr0 << 2) + j;                  // 0..15
        gidx[j] = ((row0 + tr) << LSHIFT) | (col0 + tc);
        qv[j] = __ldcs(Q + gidx[j]);
        av[j] = __ldg(type_tm + gidx[j]);
    }

    // ---- Prefetch halo-ring cell (threads 0..163) ----
    int hr = 0, hc = 0, hgidx = 0;
    float4 qh;
    int ah = 0;
    bool has_halo = (tid < NHALO);
    if (has_halo) {
        int h = tid;
        if (h < UCOLS)            { hr = 0;             hc = h;          }
        else if (h < 2 * UCOLS)   { hr = UROWS - 1;     hc = h - UCOLS;  }
        else { int s = h - 2 * UCOLS; hr = 1 + (s >> 1); hc = (s & 1) ? (UCOLS - 1) : 0; }
        int gr = (row0 - 1 + hr) & LMASK;
        int gc = (col0 - 1 + hc) & LMASK;
        hgidx = (gr << LSHIFT) | gc;
        qh = __ldcs(Q + hgidx);
        ah = __ldg(type_tm + hgidx);
    }

    // ---- Complete staging, sync ----
    #pragma unroll
    for (int k = 0; k < 2; k++)
        if (sidx[k] >= 0) s_type4[sidx[k]] = stage[k];
    __syncthreads();

    // ---- Phase 2: profit + Q update ----
    // inner cells: upd coords (tr+1, tc+1) -> type coords (tr+3, tc+4)
    #pragma unroll
    for (int j = 0; j < 4; j++) {
        int tr = (tr0 << 2) + j;
        const int* st = s_type + (tr + 3) * TSTR + (tc + 4);
        int t00  = st[0];
        int orth = st[-1] + st[1] + st[-TSTR] + st[TSTR];
        int diag = st[-TSTR - 1] + st[-TSTR + 1] + st[TSTR - 1] + st[TSTR + 1];
        int far2 = st[-2] + st[2] + st[-2 * TSTR] + st[2 * TSTR];
        int S2   = 5 * t00 + 2 * (orth + diag) + far2;
        float profit = (float)S2 * R_OVER_5 - 5.0f * (float)t00;

        float4 q = qv[j];
        int A = av[j], B = t00;
        float maxv = B ? fmaxf(q.z, q.w) : fmaxf(q.x, q.y);
        float old  = B ? (A ? q.w : q.y) : (A ? q.z : q.x);
        float upd  = ONE_MINUS_ETA * old + ETA * (profit + GAMMA * maxv);
        if (A == 0) { if (B == 0) q.x = upd; else q.y = upd; }
        else        { if (B == 0) q.z = upd; else q.w = upd; }

        s_upd[(tr + 1) * USTR + (tc + 1)] = upd;
        __stcs(Q_out + gidx[j], q);
        __stcs(profit_out + gidx[j], profit);
    }

    // halo cells: upd coords (hr, hc) -> type coords (hr+2, hc+3)
    if (has_halo) {
        const int* st = s_type + (hr + 2) * TSTR + (hc + 3);
        int t00  = st[0];
        int orth = st[-1] + st[1] + st[-TSTR] + st[TSTR];
        int diag = st[-TSTR - 1] + st[-TSTR + 1] + st[TSTR - 1] + st[TSTR + 1];
        int far2 = st[-2] + st[2] + st[-2 * TSTR] + st[2 * TSTR];
        int S2   = 5 * t00 + 2 * (orth + diag) + far2;
        float profit = (float)S2 * R_OVER_5 - 5.0f * (float)t00;

        float4 q = qh;
        int A = ah, B = t00;
        float maxv = B ? fmaxf(q.z, q.w) : fmaxf(q.x, q.y);
        float old  = B ? (A ? q.w : q.y) : (A ? q.z : q.x);
        float upd  = ONE_MINUS_ETA * old + ETA * (profit + GAMMA * maxv);
        s_upd[hr * USTR + hc] = upd;
    }
    __syncthreads();

    // ---- Phase 3: fermi from smem ----
    #pragma unroll
    for (int j = 0; j < 4; j++) {
        int tr = (tr0 << 2) + j;
        int gi = gidx[j];

        int   d = __ldcs(ldir + gi);
        float p = __ldcs(lprob + gi);

        float u = s_upd[(tr + 1) * USTR + (tc + 1)];

        int ur, uc;
        if (d == 0)      { ur = tr + 1; uc = tc;     }   // col-1
        else if (d == 1) { ur = tr + 1; uc = tc + 2; }   // col+1
        else if (d == 2) { ur = tr;     uc = tc + 1; }   // row-1
        else             { ur = tr + 2; uc = tc + 1; }   // row+1

        float un = s_upd[ur * USTR + uc];
        int tmine = s_type[(tr + 3) * TSTR + (tc + 4)];
        int tn    = s_type[(ur + 2) * TSTR + (uc + 3)];

        float W = 1.0f / (1.0f + __expf((u - un) * INV_K));
        int out = (p <= W) ? tn : tmine;
        __stcs(type_out + gi, (float)out);
    }
}

// ---------------------------------------------------------------------------
// Launch: output layout = concat(Q_new[4N], type_t1[N], profit[N]) as float32
// ---------------------------------------------------------------------------
extern "C" void kernel_launch(void* const* d_in, const int* in_sizes, int n_in,
                              void* d_out, int out_size)
{
    const int*    type_tm = (const int*)   d_in[0];
    const int*    type_t  = (const int*)   d_in[1];
    const float4* Q       = (const float4*)d_in[2];
    const int*    ldir    = (const int*)   d_in[3];
    const float*  lprob   = (const float*) d_in[4];

    float* out        = (float*)d_out;
    float4* Q_out     = (float4*)out;                 // [0, 4N)
    float* type_out   = out + 4 * (size_t)NCELL;      // [4N, 5N)
    float* profit_out = out + 5 * (size_t)NCELL;      // [5N, 6N)

    const int blocks = (Lg / TX) * (Lg / TY);         // 4096

    spgg_fused<<<blocks, 256>>>(type_tm, type_t, Q, ldir, lprob,
                                Q_out, type_out, profit_out);
}